// round 3
// baseline (speedup 1.0000x reference)
#include <cuda_runtime.h>
#include <math.h>

#define NN 20000
#define NE 320000
#define NE2 (NE + NN)
#define H 128
#define HEADS 4
#define HH 512   // HEADS*H

// ---------------- static scratch (no allocation allowed) ----------------
__device__ float g_h[NN * H];         // current node features
__device__ float g_t[NN * H];         // temp 128-wide
__device__ float g_xl[NN * HH];
__device__ float g_xr[NN * HH];
__device__ float g_agg[NN * HH];
__device__ float g_ffn[NN * 256];
__device__ float g_scores[NE2 * HEADS];
__device__ float g_la[NN * 2];        // self-loop attr (mean of incoming)
__device__ int   g_deg[NN];
__device__ int   g_rowptr[NN + 1];
__device__ int   g_cursor[NN];
__device__ int   g_csr[NE2];

// ---------------- graph setup ----------------
__global__ void zero_kernel() {
    int i = blockIdx.x * blockDim.x + threadIdx.x;
    if (i < NN) {
        g_deg[i] = 0;
        g_cursor[i] = 0;
        g_la[2 * i] = 0.f;
        g_la[2 * i + 1] = 0.f;
    }
}

__global__ void deg_kernel(const int* __restrict__ ei, const float* __restrict__ ea) {
    int e = blockIdx.x * blockDim.x + threadIdx.x;
    if (e < NE) {
        int dst = ei[NE + e];
        atomicAdd(&g_deg[dst], 1);
        atomicAdd(&g_la[2 * dst],     ea[2 * e]);
        atomicAdd(&g_la[2 * dst + 1], ea[2 * e + 1]);
    }
}

__global__ void loopattr_kernel() {
    int n = blockIdx.x * blockDim.x + threadIdx.x;
    if (n < NN) {
        float d = fmaxf((float)g_deg[n], 1.0f);
        g_la[2 * n]     /= d;
        g_la[2 * n + 1] /= d;
    }
}

// single-block inclusive scan over (deg[i]+1) -> rowptr
__global__ void scan_kernel() {
    __shared__ int sh[1024];
    int carry = 0;
    if (threadIdx.x == 0) g_rowptr[0] = 0;
    for (int base = 0; base < NN; base += 1024) {
        int i = base + (int)threadIdx.x;
        int v = (i < NN) ? (g_deg[i] + 1) : 0;
        sh[threadIdx.x] = v;
        __syncthreads();
        for (int off = 1; off < 1024; off <<= 1) {
            int t = (threadIdx.x >= (unsigned)off) ? sh[threadIdx.x - off] : 0;
            __syncthreads();
            sh[threadIdx.x] += t;
            __syncthreads();
        }
        if (i < NN) g_rowptr[i + 1] = carry + sh[threadIdx.x];
        carry += sh[1023];
        __syncthreads();
    }
}

__global__ void scatter_kernel(const int* __restrict__ ei) {
    int e = blockIdx.x * blockDim.x + threadIdx.x;
    if (e < NE2) {
        int dst = (e < NE) ? ei[NE + e] : (e - NE);
        int pos = atomicAdd(&g_cursor[dst], 1);
        g_csr[g_rowptr[dst] + pos] = e;
    }
}

// ---------------- generic tiled GEMM: C = act(A[n,K] @ B[K,M] + bias) ----------------
// 64x64 tile, BK=16, 256 threads, 4x4 per thread. K%16==0, M%64==0 assumed.
__global__ void gemm_kernel(const float* __restrict__ A, const float* __restrict__ B,
                            const float* __restrict__ bias, float* __restrict__ C,
                            int n, int K, int M, int act) {
    __shared__ float As[16][64];
    __shared__ float Bs[16][64];
    int tid = threadIdx.x;
    int tx = tid & 15, ty = tid >> 4;
    int row0 = blockIdx.x * 64;
    int col0 = blockIdx.y * 64;

    float acc[4][4];
#pragma unroll
    for (int i = 0; i < 4; i++)
#pragma unroll
        for (int j = 0; j < 4; j++) acc[i][j] = 0.f;

    for (int kb = 0; kb < K; kb += 16) {
        {
            int m = tid >> 2, q = tid & 3;
            int gr = row0 + m;
            float4 av = make_float4(0.f, 0.f, 0.f, 0.f);
            if (gr < n) av = *(const float4*)&A[(size_t)gr * K + kb + q * 4];
            As[q * 4 + 0][m] = av.x;
            As[q * 4 + 1][m] = av.y;
            As[q * 4 + 2][m] = av.z;
            As[q * 4 + 3][m] = av.w;
            int kk = tid >> 4, q2 = tid & 15;
            float4 bv = *(const float4*)&B[(size_t)(kb + kk) * M + col0 + q2 * 4];
            *(float4*)&Bs[kk][q2 * 4] = bv;
        }
        __syncthreads();
#pragma unroll
        for (int k = 0; k < 16; k++) {
            float a[4], b[4];
#pragma unroll
            for (int i = 0; i < 4; i++) a[i] = As[k][ty * 4 + i];
#pragma unroll
            for (int j = 0; j < 4; j++) b[j] = Bs[k][tx * 4 + j];
#pragma unroll
            for (int i = 0; i < 4; i++)
#pragma unroll
                for (int j = 0; j < 4; j++) acc[i][j] += a[i] * b[j];
        }
        __syncthreads();
    }

#pragma unroll
    for (int i = 0; i < 4; i++) {
        int r = row0 + ty * 4 + i;
        if (r >= n) continue;
#pragma unroll
        for (int j = 0; j < 4; j++) {
            int c = col0 + tx * 4 + j;
            float v = acc[i][j];
            if (bias) v += __ldg(&bias[c]);
            if (act == 1) {  // exact gelu
                v = 0.5f * v * (1.0f + erff(v * 0.70710678118654752f));
            }
            C[(size_t)r * M + c] = v;
        }
    }
}

// ---------------- edge scores: one warp per (edge, head) ----------------
__global__ void edge_score_kernel(const int* __restrict__ ei, const float* __restrict__ ea,
                                  const float* __restrict__ We, const float* __restrict__ att) {
    int gw = (blockIdx.x * blockDim.x + threadIdx.x) >> 5;
    int lane = threadIdx.x & 31;
    if (gw >= NE2 * HEADS) return;
    int e = gw >> 2, h = gw & 3;

    int src, dst;
    float a0, a1;
    if (e < NE) {
        src = __ldg(&ei[e]);
        dst = __ldg(&ei[NE + e]);
        a0 = __ldg(&ea[2 * e]);
        a1 = __ldg(&ea[2 * e + 1]);
    } else {
        src = dst = e - NE;
        a0 = g_la[2 * src];
        a1 = g_la[2 * src + 1];
    }

    const float* xls = g_xl + (size_t)src * HH + h * H;
    const float* xrd = g_xr + (size_t)dst * HH + h * H;
    const float* w0 = We + h * H;
    const float* w1 = We + HH + h * H;
    const float* at = att + h * H;

    float p = 0.f;
#pragma unroll
    for (int k = 0; k < 4; k++) {
        int c = lane + 32 * k;
        float v = xls[c] + xrd[c] + a0 * __ldg(&w0[c]) + a1 * __ldg(&w1[c]);
        v = v > 0.f ? v : 0.2f * v;
        p += v * __ldg(&at[c]);
    }
#pragma unroll
    for (int o = 16; o; o >>= 1) p += __shfl_xor_sync(0xffffffffu, p, o);
    if (lane == 0) g_scores[e * 4 + h] = p;
}

// ---------------- segment softmax + weighted aggregation: warp per (node, head) ----------------
__global__ void agg_kernel(const int* __restrict__ ei, const float* __restrict__ bias) {
    int gw = (blockIdx.x * blockDim.x + threadIdx.x) >> 5;
    int lane = threadIdx.x & 31;
    if (gw >= NN * HEADS) return;
    int n = gw >> 2, h = gw & 3;
    int beg = g_rowptr[n], end = g_rowptr[n + 1];

    float m = -1e30f;
    for (int j = beg + lane; j < end; j += 32) m = fmaxf(m, g_scores[g_csr[j] * 4 + h]);
#pragma unroll
    for (int o = 16; o; o >>= 1) m = fmaxf(m, __shfl_xor_sync(0xffffffffu, m, o));

    float s = 0.f;
    for (int j = beg + lane; j < end; j += 32) s += expf(g_scores[g_csr[j] * 4 + h] - m);
#pragma unroll
    for (int o = 16; o; o >>= 1) s += __shfl_xor_sync(0xffffffffu, s, o);
    float inv = 1.0f / (s + 1e-16f);

    float acc0 = 0.f, acc1 = 0.f, acc2 = 0.f, acc3 = 0.f;
    for (int j = beg; j < end; j++) {
        int eid = g_csr[j];
        float alpha = expf(g_scores[eid * 4 + h] - m) * inv;
        int src = (eid < NE) ? __ldg(&ei[eid]) : (eid - NE);
        const float* xs = g_xl + (size_t)src * HH + h * H + lane;
        acc0 += alpha * __ldg(xs);
        acc1 += alpha * __ldg(xs + 32);
        acc2 += alpha * __ldg(xs + 64);
        acc3 += alpha * __ldg(xs + 96);
    }

    float b0 = 0.f, b1 = 0.f, b2 = 0.f, b3 = 0.f;
    if (bias) {
        b0 = __ldg(&bias[h * H + lane]);
        b1 = __ldg(&bias[h * H + lane + 32]);
        b2 = __ldg(&bias[h * H + lane + 64]);
        b3 = __ldg(&bias[h * H + lane + 96]);
    }
    float* o = g_agg + (size_t)n * HH + h * H + lane;
    o[0]  = acc0 + b0;
    o[32] = acc1 + b1;
    o[64] = acc2 + b2;
    o[96] = acc3 + b3;
}

// layer-2: mean over heads + bias
__global__ void headmean_kernel(const float* __restrict__ bias2) {
    int idx = blockIdx.x * blockDim.x + threadIdx.x;
    if (idx >= NN * H) return;
    int n = idx >> 7, c = idx & 127;
    const float* a = g_agg + (size_t)n * HH;
    g_t[idx] = 0.25f * (a[c] + a[H + c] + a[2 * H + c] + a[3 * H + c]) + __ldg(&bias2[c]);
}

// LayerNorm(out = LN(a + res) * g + b), 128 threads per node
__global__ void ln_kernel(const float* __restrict__ a, const float* __restrict__ res,
                          const float* __restrict__ g, const float* __restrict__ b,
                          float* __restrict__ out) {
    __shared__ float sh[128];
    int n = blockIdx.x;
    int c = threadIdx.x;
    float v = a[(size_t)n * H + c] + res[(size_t)n * H + c];
    sh[c] = v;
    __syncthreads();
    for (int off = 64; off > 0; off >>= 1) {
        if (c < off) sh[c] += sh[c + off];
        __syncthreads();
    }
    float mu = sh[0] * (1.0f / 128.0f);
    __syncthreads();
    float d = v - mu;
    sh[c] = d * d;
    __syncthreads();
    for (int off = 64; off > 0; off >>= 1) {
        if (c < off) sh[c] += sh[c + off];
        __syncthreads();
    }
    float var = sh[0] * (1.0f / 128.0f);
    out[(size_t)n * H + c] = d * rsqrtf(var + 1e-5f) * __ldg(&g[c]) + __ldg(&b[c]);
}

// ---------------- host ----------------
static void* sym(const void* s) {
    void* p = 0;
    cudaGetSymbolAddress(&p, s);
    return p;
}

extern "C" void kernel_launch(void* const* d_in, const int* in_sizes, int n_in,
                              void* d_out, int out_size) {
    const float* x        = (const float*)d_in[0];
    const int*   ei       = (const int*)d_in[1];
    const float* ea       = (const float*)d_in[2];
    const float* emb_w    = (const float*)d_in[3];
    const float* emb_b    = (const float*)d_in[4];
    const float* lin_l    = (const float*)d_in[5];
    const float* lin_r    = (const float*)d_in[6];
    const float* lin_edge = (const float*)d_in[7];
    const float* att      = (const float*)d_in[8];
    const float* cbias01  = (const float*)d_in[9];
    const float* cbias2   = (const float*)d_in[10];
    const float* proj_w   = (const float*)d_in[11];
    const float* proj_b   = (const float*)d_in[12];
    const float* n1_g     = (const float*)d_in[13];
    const float* n1_b     = (const float*)d_in[14];
    const float* n2_g     = (const float*)d_in[15];
    const float* n2_b     = (const float*)d_in[16];
    const float* ffn_w1   = (const float*)d_in[17];
    const float* ffn_b1   = (const float*)d_in[18];
    const float* ffn_w2   = (const float*)d_in[19];
    const float* ffn_b2   = (const float*)d_in[20];

    float* p_h   = (float*)sym(g_h);
    float* p_t   = (float*)sym(g_t);
    float* p_xl  = (float*)sym(g_xl);
    float* p_xr  = (float*)sym(g_xr);
    float* p_agg = (float*)sym(g_agg);
    float* p_ffn = (float*)sym(g_ffn);

    // graph setup
    zero_kernel<<<(NN + 255) / 256, 256>>>();
    deg_kernel<<<(NE + 255) / 256, 256>>>(ei, ea);
    loopattr_kernel<<<(NN + 255) / 256, 256>>>();
    scan_kernel<<<1, 1024>>>();
    scatter_kernel<<<(NE2 + 255) / 256, 256>>>(ei);

    // embedding: h = x @ emb_w + emb_b
    {
        dim3 grid((NN + 63) / 64, H / 64);
        gemm_kernel<<<grid, 256>>>(x, emb_w, emb_b, p_h, NN, 16, H, 0);
    }

    for (int i = 0; i < 3; i++) {
        const float* Wl = lin_l + (size_t)i * H * HH;
        const float* Wr = lin_r + (size_t)i * H * HH;
        const float* We = lin_edge + (size_t)i * 2 * HH;
        const float* At = att + (size_t)i * HEADS * H;

        dim3 g512((NN + 63) / 64, HH / 64);
        gemm_kernel<<<g512, 256>>>(p_h, Wl, 0, p_xl, NN, H, HH, 0);
        gemm_kernel<<<g512, 256>>>(p_h, Wr, 0, p_xr, NN, H, HH, 0);

        {
            long warps = (long)NE2 * HEADS;
            long thr = warps * 32;
            edge_score_kernel<<<(int)((thr + 255) / 256), 256>>>(ei, ea, We, At);
        }
        {
            long warps = (long)NN * HEADS;
            long thr = warps * 32;
            const float* bias = (i < 2) ? (cbias01 + (size_t)i * HH) : 0;
            agg_kernel<<<(int)((thr + 255) / 256), 256>>>(ei, bias);
        }

        if (i < 2) {
            dim3 gp((NN + 63) / 64, H / 64);
            gemm_kernel<<<gp, 256>>>(p_agg, proj_w + (size_t)i * HH * H,
                                     proj_b + (size_t)i * H, p_t, NN, HH, H, 0);
        } else {
            headmean_kernel<<<(NN * H + 255) / 256, 256>>>(cbias2);
        }

        ln_kernel<<<NN, 128>>>(p_t, p_h, n1_g + (size_t)i * H, n1_b + (size_t)i * H, p_h);

        dim3 gf1((NN + 63) / 64, 256 / 64);
        gemm_kernel<<<gf1, 256>>>(p_h, ffn_w1 + (size_t)i * H * 256,
                                  ffn_b1 + (size_t)i * 256, p_ffn, NN, H, 256, 1);
        dim3 gf2((NN + 63) / 64, H / 64);
        gemm_kernel<<<gf2, 256>>>(p_ffn, ffn_w2 + (size_t)i * 256 * H,
                                  ffn_b2 + (size_t)i * H, p_t, NN, 256, H, 0);

        float* out_ptr = (i == 2) ? (float*)d_out : p_h;
        ln_kernel<<<NN, 128>>>(p_t, p_h, n2_g + (size_t)i * H, n2_b + (size_t)i * H, out_ptr);
    }
}

// round 6
// speedup vs baseline: 1.2914x; 1.2914x over previous
#include <cuda_runtime.h>
#include <math.h>

#define NN 20000
#define NE 320000
#define NE2 (NE + NN)
#define H 128
#define HEADS 4
#define HH 512   // HEADS*H

// ---------------- static scratch (no allocation allowed) ----------------
__device__ float g_h[NN * H];
__device__ float g_t[NN * H];
__device__ float g_xl[NN * HH];
__device__ float g_xr[NN * HH];
__device__ float g_agg[NN * HH];
__device__ float g_ffn[NN * 256];
__device__ float g_scores[NE2 * HEADS];
__device__ float g_la[NN * 2];
__device__ int   g_deg[NN];
__device__ int   g_rowptr[NN + 1];
__device__ int   g_cursor[NN];
__device__ int   g_csr[NE2];
__device__ int   g_bsum[32];

// ---------------- graph setup ----------------
__global__ void zero_kernel() {
    int i = blockIdx.x * blockDim.x + threadIdx.x;
    if (i < NN) {
        g_deg[i] = 0;
        g_cursor[i] = 0;
        g_la[2 * i] = 0.f;
        g_la[2 * i + 1] = 0.f;
    }
}

__global__ void deg_kernel(const int* __restrict__ ei, const float* __restrict__ ea) {
    int e = blockIdx.x * blockDim.x + threadIdx.x;
    if (e < NE) {
        int dst = ei[NE + e];
        atomicAdd(&g_deg[dst], 1);
        atomicAdd(&g_la[2 * dst],     ea[2 * e]);
        atomicAdd(&g_la[2 * dst + 1], ea[2 * e + 1]);
    }
}

__global__ void loopattr_kernel() {
    int n = blockIdx.x * blockDim.x + threadIdx.x;
    if (n < NN) {
        float d = fmaxf((float)g_deg[n], 1.0f);
        g_la[2 * n]     /= d;
        g_la[2 * n + 1] /= d;
    }
}

// multi-block scan over (deg[i]+1) -> rowptr.  scan1: per-block inclusive scan
__global__ void scan1_kernel() {
    __shared__ int ws[32];
    int b = blockIdx.x, t = threadIdx.x;
    int i = b * 1024 + t;
    int lane = t & 31, w = t >> 5;
    int x = (i < NN) ? (g_deg[i] + 1) : 0;
#pragma unroll
    for (int o = 1; o < 32; o <<= 1) {
        int y = __shfl_up_sync(0xffffffffu, x, o);
        if (lane >= o) x += y;
    }
    if (lane == 31) ws[w] = x;
    __syncthreads();
    if (w == 0) {
        int s = ws[lane];
#pragma unroll
        for (int o = 1; o < 32; o <<= 1) {
            int y = __shfl_up_sync(0xffffffffu, s, o);
            if (lane >= o) s += y;
        }
        ws[lane] = s;
    }
    __syncthreads();
    int off = (w > 0) ? ws[w - 1] : 0;
    x += off;
    if (i < NN) g_rowptr[i + 1] = x;
    if (t == 1023) g_bsum[b] = ws[31];
    if (b == 0 && t == 0) g_rowptr[0] = 0;
}

__global__ void scan2_kernel(int nblk) {
    int t = threadIdx.x;
    int v = (t < nblk) ? g_bsum[t] : 0;
#pragma unroll
    for (int o = 1; o < 32; o <<= 1) {
        int y = __shfl_up_sync(0xffffffffu, v, o);
        if (t >= o) v += y;
    }
    if (t < nblk) g_bsum[t] = v;   // inclusive
}

__global__ void scan3_kernel() {
    int i = blockIdx.x * blockDim.x + threadIdx.x;
    if (i >= NN) return;
    int b = i >> 10;
    if (b > 0) g_rowptr[i + 1] += g_bsum[b - 1];
}

__global__ void scatter_kernel(const int* __restrict__ ei) {
    int e = blockIdx.x * blockDim.x + threadIdx.x;
    if (e < NE2) {
        int dst = (e < NE) ? ei[NE + e] : (e - NE);
        int pos = atomicAdd(&g_cursor[dst], 1);
        g_csr[g_rowptr[dst] + pos] = e;
    }
}

// ---------------- TF32 tensor-core GEMM (3xTF32 compensated) ----------------
// C[n,N] = act(A[n,K] @ B[K,N] + bias). K%16==0, N%64==0.
#define BM 128
#define BN 64
#define BK 16
#define SA 20   // As row stride (conflict-free fragment loads: 20*g+tg distinct mod 32)
#define SB 72   // Bs row stride (72*tg+g -> 8*tg+g distinct mod 32)

__device__ __forceinline__ unsigned f2tf(float f) {
    unsigned r;
    asm("cvt.rna.tf32.f32 %0, %1;" : "=r"(r) : "f"(f));
    return r;
}

__device__ __forceinline__ void mma8(float c[4], const unsigned a[4], unsigned b0, unsigned b1) {
    asm volatile(
        "mma.sync.aligned.m16n8k8.row.col.f32.tf32.tf32.f32 "
        "{%0,%1,%2,%3}, {%4,%5,%6,%7}, {%8,%9}, {%0,%1,%2,%3};"
        : "+f"(c[0]), "+f"(c[1]), "+f"(c[2]), "+f"(c[3])
        : "r"(a[0]), "r"(a[1]), "r"(a[2]), "r"(a[3]), "r"(b0), "r"(b1));
}

__global__ __launch_bounds__(256) void mma_gemm(const float* __restrict__ A,
                                                const float* __restrict__ B,
                                                const float* __restrict__ bias,
                                                float* __restrict__ C,
                                                int n, int K, int N, int act) {
    __shared__ float As[BM][SA];
    __shared__ float Bs[BK][SB];
    int tid = threadIdx.x;
    int warp = tid >> 5, lane = tid & 31;
    int g = lane >> 2, tg = lane & 3;
    int wm = warp >> 1, wn = warp & 1;
    int row0 = blockIdx.x * BM, col0 = blockIdx.y * BN;

    float c[2][4][4];
#pragma unroll
    for (int mi = 0; mi < 2; mi++)
#pragma unroll
        for (int ni = 0; ni < 4; ni++)
#pragma unroll
            for (int q = 0; q < 4; q++) c[mi][ni][q] = 0.f;

    for (int kb = 0; kb < K; kb += BK) {
        // load A tile: 128x16 -> As[m][k]
#pragma unroll
        for (int p = 0; p < 2; p++) {
            int fi = tid + p * 256;
            int r = fi >> 2, q = fi & 3;
            int gr = row0 + r;
            float4 v = make_float4(0.f, 0.f, 0.f, 0.f);
            if (gr < n) v = *(const float4*)&A[(size_t)gr * K + kb + q * 4];
            As[r][q * 4 + 0] = v.x;
            As[r][q * 4 + 1] = v.y;
            As[r][q * 4 + 2] = v.z;
            As[r][q * 4 + 3] = v.w;
        }
        // load B tile: 16x64 -> Bs[k][nn]
        {
            int r = tid >> 4, q = tid & 15;
            float4 v = *(const float4*)&B[(size_t)(kb + r) * N + col0 + q * 4];
            Bs[r][q * 4 + 0] = v.x;
            Bs[r][q * 4 + 1] = v.y;
            Bs[r][q * 4 + 2] = v.z;
            Bs[r][q * 4 + 3] = v.w;
        }
        __syncthreads();

#pragma unroll
        for (int ks = 0; ks < 2; ks++) {
            int k0 = ks * 8;
            unsigned ah[2][4], al[2][4];
#pragma unroll
            for (int mi = 0; mi < 2; mi++) {
                int mrow = wm * 32 + mi * 16;
                float f0 = As[mrow + g][k0 + tg];
                float f1 = As[mrow + g + 8][k0 + tg];
                float f2 = As[mrow + g][k0 + tg + 4];
                float f3 = As[mrow + g + 8][k0 + tg + 4];
                ah[mi][0] = f2tf(f0); al[mi][0] = f2tf(f0 - __uint_as_float(ah[mi][0]));
                ah[mi][1] = f2tf(f1); al[mi][1] = f2tf(f1 - __uint_as_float(ah[mi][1]));
                ah[mi][2] = f2tf(f2); al[mi][2] = f2tf(f2 - __uint_as_float(ah[mi][2]));
                ah[mi][3] = f2tf(f3); al[mi][3] = f2tf(f3 - __uint_as_float(ah[mi][3]));
            }
#pragma unroll
            for (int ni = 0; ni < 4; ni++) {
                int ncol = wn * 32 + ni * 8 + g;
                float fb0 = Bs[k0 + tg][ncol];
                float fb1 = Bs[k0 + tg + 4][ncol];
                unsigned bh0 = f2tf(fb0), bl0 = f2tf(fb0 - __uint_as_float(bh0));
                unsigned bh1 = f2tf(fb1), bl1 = f2tf(fb1 - __uint_as_float(bh1));
#pragma unroll
                for (int mi = 0; mi < 2; mi++) {
                    mma8(c[mi][ni], ah[mi], bh0, bh1);   // hi*hi
                    mma8(c[mi][ni], al[mi], bh0, bh1);   // lo*hi
                    mma8(c[mi][ni], ah[mi], bl0, bl1);   // hi*lo
                }
            }
        }
        __syncthreads();
    }

    // epilogue
#pragma unroll
    for (int mi = 0; mi < 2; mi++) {
#pragma unroll
        for (int ni = 0; ni < 4; ni++) {
            int r = row0 + wm * 32 + mi * 16 + g;
            int col = col0 + wn * 32 + ni * 8 + tg * 2;
            float b0v = bias ? __ldg(&bias[col]) : 0.f;
            float b1v = bias ? __ldg(&bias[col + 1]) : 0.f;
            if (r < n) {
                float v0 = c[mi][ni][0] + b0v;
                float v1 = c[mi][ni][1] + b1v;
                if (act) {
                    v0 = 0.5f * v0 * (1.0f + erff(v0 * 0.70710678118654752f));
                    v1 = 0.5f * v1 * (1.0f + erff(v1 * 0.70710678118654752f));
                }
                C[(size_t)r * N + col]     = v0;
                C[(size_t)r * N + col + 1] = v1;
            }
            if (r + 8 < n) {
                float v2 = c[mi][ni][2] + b0v;
                float v3 = c[mi][ni][3] + b1v;
                if (act) {
                    v2 = 0.5f * v2 * (1.0f + erff(v2 * 0.70710678118654752f));
                    v3 = 0.5f * v3 * (1.0f + erff(v3 * 0.70710678118654752f));
                }
                C[(size_t)(r + 8) * N + col]     = v2;
                C[(size_t)(r + 8) * N + col + 1] = v3;
            }
        }
    }
}

// ---------------- fused GATv2: score + segment softmax + aggregation ----------------
// one warp per (node, head); xr[dst], We, att slices live in registers.
__global__ void gat_fused_kernel(const int* __restrict__ ei, const float* __restrict__ ea,
                                 const float* __restrict__ We, const float* __restrict__ att,
                                 const float* __restrict__ bias) {
    int gw = (blockIdx.x * blockDim.x + threadIdx.x) >> 5;
    int lane = threadIdx.x & 31;
    if (gw >= NN * HEADS) return;
    int n = gw >> 2, h = gw & 3;
    int beg = g_rowptr[n], end = g_rowptr[n + 1];

    float xr[4], w0[4], w1[4], at[4];
#pragma unroll
    for (int k = 0; k < 4; k++) {
        int cc = h * H + lane + 32 * k;
        xr[k] = g_xr[(size_t)n * HH + cc];
        w0[k] = __ldg(&We[cc]);
        w1[k] = __ldg(&We[HH + cc]);
        at[k] = __ldg(&att[cc]);
    }
    float la0 = g_la[2 * n], la1 = g_la[2 * n + 1];

    // pass 1: scores + max
    float m = -1e30f;
    for (int j = beg; j < end; j++) {
        int e = g_csr[j];
        int src; float a0, a1;
        if (e < NE) {
            src = __ldg(&ei[e]);
            a0 = __ldg(&ea[2 * e]);
            a1 = __ldg(&ea[2 * e + 1]);
        } else {
            src = n; a0 = la0; a1 = la1;
        }
        const float* xs = g_xl + (size_t)src * HH + h * H + lane;
        float p = 0.f;
#pragma unroll
        for (int k = 0; k < 4; k++) {
            float v = __ldg(xs + 32 * k) + xr[k] + a0 * w0[k] + a1 * w1[k];
            v = v > 0.f ? v : 0.2f * v;
            p += v * at[k];
        }
#pragma unroll
        for (int o = 16; o; o >>= 1) p += __shfl_xor_sync(0xffffffffu, p, o);
        if (lane == 0) g_scores[j * 4 + h] = p;
        m = fmaxf(m, p);
    }
    __syncwarp();

    // pass 2: denom + weighted sum together (normalize at end)
    float denom = 0.f;
    float acc[4] = {0.f, 0.f, 0.f, 0.f};
    for (int j = beg; j < end; j++) {
        int e = g_csr[j];
        int src = (e < NE) ? __ldg(&ei[e]) : n;
        float p = expf(g_scores[j * 4 + h] - m);
        denom += p;
        const float* xs = g_xl + (size_t)src * HH + h * H + lane;
#pragma unroll
        for (int k = 0; k < 4; k++) acc[k] += p * __ldg(xs + 32 * k);
    }
    float inv = 1.0f / (denom + 1e-16f);

    float* o = g_agg + (size_t)n * HH + h * H + lane;
#pragma unroll
    for (int k = 0; k < 4; k++) {
        float bv = bias ? __ldg(&bias[h * H + lane + 32 * k]) : 0.f;
        o[32 * k] = acc[k] * inv + bv;
    }
}

// layer-2: mean over heads + bias
__global__ void headmean_kernel(const float* __restrict__ bias2) {
    int idx = blockIdx.x * blockDim.x + threadIdx.x;
    if (idx >= NN * H) return;
    int n = idx >> 7, c = idx & 127;
    const float* a = g_agg + (size_t)n * HH;
    g_t[idx] = 0.25f * (a[c] + a[H + c] + a[2 * H + c] + a[3 * H + c]) + __ldg(&bias2[c]);
}

// warp-per-node LayerNorm: out = LN(a + res) * g + b
__global__ void ln_kernel(const float* __restrict__ a, const float* __restrict__ res,
                          const float* __restrict__ g, const float* __restrict__ b,
                          float* __restrict__ out) {
    int gw = (blockIdx.x * blockDim.x + threadIdx.x) >> 5;
    int lane = threadIdx.x & 31;
    if (gw >= NN) return;
    const float* pa = a + (size_t)gw * H;
    const float* pr = res + (size_t)gw * H;
    float v[4];
    float s = 0.f;
#pragma unroll
    for (int k = 0; k < 4; k++) {
        v[k] = pa[lane + 32 * k] + pr[lane + 32 * k];
        s += v[k];
    }
#pragma unroll
    for (int o = 16; o; o >>= 1) s += __shfl_xor_sync(0xffffffffu, s, o);
    float mu = s * (1.0f / 128.0f);
    float q = 0.f;
#pragma unroll
    for (int k = 0; k < 4; k++) {
        float d = v[k] - mu;
        q += d * d;
    }
#pragma unroll
    for (int o = 16; o; o >>= 1) q += __shfl_xor_sync(0xffffffffu, q, o);
    float r = rsqrtf(q * (1.0f / 128.0f) + 1e-5f);
    float* po = out + (size_t)gw * H;
#pragma unroll
    for (int k = 0; k < 4; k++) {
        int cc = lane + 32 * k;
        po[cc] = (v[k] - mu) * r * __ldg(&g[cc]) + __ldg(&b[cc]);
    }
}

// ---------------- host ----------------
static void* sym(const void* s) {
    void* p = 0;
    cudaGetSymbolAddress(&p, s);
    return p;
}

extern "C" void kernel_launch(void* const* d_in, const int* in_sizes, int n_in,
                              void* d_out, int out_size) {
    const float* x        = (const float*)d_in[0];
    const int*   ei       = (const int*)d_in[1];
    const float* ea       = (const float*)d_in[2];
    const float* emb_w    = (const float*)d_in[3];
    const float* emb_b    = (const float*)d_in[4];
    const float* lin_l    = (const float*)d_in[5];
    const float* lin_r    = (const float*)d_in[6];
    const float* lin_edge = (const float*)d_in[7];
    const float* att      = (const float*)d_in[8];
    const float* cbias01  = (const float*)d_in[9];
    const float* cbias2   = (const float*)d_in[10];
    const float* proj_w   = (const float*)d_in[11];
    const float* proj_b   = (const float*)d_in[12];
    const float* n1_g     = (const float*)d_in[13];
    const float* n1_b     = (const float*)d_in[14];
    const float* n2_g     = (const float*)d_in[15];
    const float* n2_b     = (const float*)d_in[16];
    const float* ffn_w1   = (const float*)d_in[17];
    const float* ffn_b1   = (const float*)d_in[18];
    const float* ffn_w2   = (const float*)d_in[19];
    const float* ffn_b2   = (const float*)d_in[20];

    float* p_h   = (float*)sym(g_h);
    float* p_t   = (float*)sym(g_t);
    float* p_xl  = (float*)sym(g_xl);
    float* p_xr  = (float*)sym(g_xr);
    float* p_agg = (float*)sym(g_agg);
    float* p_ffn = (float*)sym(g_ffn);

    // graph setup
    int nblk = (NN + 1023) / 1024;
    zero_kernel<<<(NN + 255) / 256, 256>>>();
    deg_kernel<<<(NE + 255) / 256, 256>>>(ei, ea);
    loopattr_kernel<<<(NN + 255) / 256, 256>>>();
    scan1_kernel<<<nblk, 1024>>>();
    scan2_kernel<<<1, 32>>>(nblk);
    scan3_kernel<<<(NN + 255) / 256, 256>>>();
    scatter_kernel<<<(NE2 + 255) / 256, 256>>>(ei);

    // embedding: h = x @ emb_w + emb_b
    {
        dim3 grid((NN + BM - 1) / BM, H / BN);
        mma_gemm<<<grid, 256>>>(x, emb_w, emb_b, p_h, NN, 16, H, 0);
    }

    for (int i = 0; i < 3; i++) {
        const float* Wl = lin_l + (size_t)i * H * HH;
        const float* Wr = lin_r + (size_t)i * H * HH;
        const float* We = lin_edge + (size_t)i * 2 * HH;
        const float* At = att + (size_t)i * HEADS * H;

        dim3 g512((NN + BM - 1) / BM, HH / BN);
        mma_gemm<<<g512, 256>>>(p_h, Wl, 0, p_xl, NN, H, HH, 0);
        mma_gemm<<<g512, 256>>>(p_h, Wr, 0, p_xr, NN, H, HH, 0);

        {
            long warps = (long)NN * HEADS;
            long thr = warps * 32;
            const float* bias = (i < 2) ? (cbias01 + (size_t)i * HH) : 0;
            gat_fused_kernel<<<(int)((thr + 255) / 256), 256>>>(ei, ea, We, At, bias);
        }

        if (i < 2) {
            dim3 gp((NN + BM - 1) / BM, H / BN);
            mma_gemm<<<gp, 256>>>(p_agg, proj_w + (size_t)i * HH * H,
                                  proj_b + (size_t)i * H, p_t, NN, HH, H, 0);
        } else {
            headmean_kernel<<<(NN * H + 255) / 256, 256>>>(cbias2);
        }

        ln_kernel<<<(NN * 32 + 255) / 256, 256>>>(p_t, p_h, n1_g + (size_t)i * H,
                                                  n1_b + (size_t)i * H, p_h);

        dim3 gf1((NN + BM - 1) / BM, 256 / BN);
        mma_gemm<<<gf1, 256>>>(p_h, ffn_w1 + (size_t)i * H * 256,
                               ffn_b1 + (size_t)i * 256, p_ffn, NN, H, 256, 1);
        dim3 gf2((NN + BM - 1) / BM, H / BN);
        mma_gemm<<<gf2, 256>>>(p_ffn, ffn_w2 + (size_t)i * 256 * H,
                               ffn_b2 + (size_t)i * H, p_t, NN, 256, H, 0);

        float* out_ptr = (i == 2) ? (float*)d_out : p_h;
        ln_kernel<<<(NN * 32 + 255) / 256, 256>>>(p_t, p_h, n2_g + (size_t)i * H,
                                                  n2_b + (size_t)i * H, out_ptr);
    }
}

// round 7
// speedup vs baseline: 1.7758x; 1.3751x over previous
#include <cuda_runtime.h>
#include <cuda_bf16.h>
#include <math.h>

#define NN 20000
#define NE 320000
#define NE2 (NE + NN)
#define H 128
#define HEADS 4
#define HH 512   // HEADS*H

// ---------------- static scratch (no allocation allowed) ----------------
__device__ float g_h[NN * H];
__device__ float g_t[NN * H];
__device__ float g_xl[NN * HH];
__device__ float g_xr[NN * HH];
__device__ float g_agg[NN * HH];
__device__ float g_ffn[NN * 256];
__device__ float g_la[NN * 2];
__device__ int   g_deg[NN];
__device__ int   g_rowptr[NN + 1];
__device__ int   g_cursor[NN];
__device__ int   g_csr[NE2];
__device__ int   g_bsum[32];

// ---------------- graph setup ----------------
__global__ void zero_kernel() {
    int i = blockIdx.x * blockDim.x + threadIdx.x;
    if (i < NN) {
        g_deg[i] = 0;
        g_cursor[i] = 0;
        g_la[2 * i] = 0.f;
        g_la[2 * i + 1] = 0.f;
    }
}

__global__ void deg_kernel(const int* __restrict__ ei, const float* __restrict__ ea) {
    int e = blockIdx.x * blockDim.x + threadIdx.x;
    if (e < NE) {
        int dst = ei[NE + e];
        atomicAdd(&g_deg[dst], 1);
        atomicAdd(&g_la[2 * dst],     ea[2 * e]);
        atomicAdd(&g_la[2 * dst + 1], ea[2 * e + 1]);
    }
}

__global__ void loopattr_kernel() {
    int n = blockIdx.x * blockDim.x + threadIdx.x;
    if (n < NN) {
        float d = fmaxf((float)g_deg[n], 1.0f);
        g_la[2 * n]     /= d;
        g_la[2 * n + 1] /= d;
    }
}

__global__ void scan1_kernel() {
    __shared__ int ws[32];
    int b = blockIdx.x, t = threadIdx.x;
    int i = b * 1024 + t;
    int lane = t & 31, w = t >> 5;
    int x = (i < NN) ? (g_deg[i] + 1) : 0;
#pragma unroll
    for (int o = 1; o < 32; o <<= 1) {
        int y = __shfl_up_sync(0xffffffffu, x, o);
        if (lane >= o) x += y;
    }
    if (lane == 31) ws[w] = x;
    __syncthreads();
    if (w == 0) {
        int s = ws[lane];
#pragma unroll
        for (int o = 1; o < 32; o <<= 1) {
            int y = __shfl_up_sync(0xffffffffu, s, o);
            if (lane >= o) s += y;
        }
        ws[lane] = s;
    }
    __syncthreads();
    int off = (w > 0) ? ws[w - 1] : 0;
    x += off;
    if (i < NN) g_rowptr[i + 1] = x;
    if (t == 1023) g_bsum[b] = ws[31];
    if (b == 0 && t == 0) g_rowptr[0] = 0;
}

__global__ void scan2_kernel(int nblk) {
    int t = threadIdx.x;
    int v = (t < nblk) ? g_bsum[t] : 0;
#pragma unroll
    for (int o = 1; o < 32; o <<= 1) {
        int y = __shfl_up_sync(0xffffffffu, v, o);
        if (t >= o) v += y;
    }
    if (t < nblk) g_bsum[t] = v;
}

__global__ void scan3_kernel() {
    int i = blockIdx.x * blockDim.x + threadIdx.x;
    if (i >= NN) return;
    int b = i >> 10;
    if (b > 0) g_rowptr[i + 1] += g_bsum[b - 1];
}

__global__ void scatter_kernel(const int* __restrict__ ei) {
    int e = blockIdx.x * blockDim.x + threadIdx.x;
    if (e < NE2) {
        int dst = (e < NE) ? ei[NE + e] : (e - NE);
        int pos = atomicAdd(&g_cursor[dst], 1);
        g_csr[g_rowptr[dst] + pos] = e;
    }
}

// ---------------- split-bf16 tensor-core GEMM (3-pass compensated) ----------------
// C[n,N] = act(A[n,K] @ B[K,N] + bias). K%16==0, N%64==0.
#define BM 128
#define BN 64
#define BK 16
#define SAH 24   // A smem row stride in halves (48B rows: ldmatrix phase conflict-free)
#define SBH 72   // B smem row stride in halves (144B rows: stride 36 words == 4 mod 32)

__device__ __forceinline__ unsigned smaddr(const void* p) {
    return (unsigned)__cvta_generic_to_shared(p);
}

__device__ __forceinline__ void ldsm_x4(unsigned r[4], const void* p) {
    unsigned a = smaddr(p);
    asm volatile("ldmatrix.sync.aligned.m8n8.x4.shared.b16 {%0,%1,%2,%3},[%4];"
                 : "=r"(r[0]), "=r"(r[1]), "=r"(r[2]), "=r"(r[3]) : "r"(a));
}

__device__ __forceinline__ void ldsm_x4_t(unsigned r[4], const void* p) {
    unsigned a = smaddr(p);
    asm volatile("ldmatrix.sync.aligned.m8n8.x4.trans.shared.b16 {%0,%1,%2,%3},[%4];"
                 : "=r"(r[0]), "=r"(r[1]), "=r"(r[2]), "=r"(r[3]) : "r"(a));
}

__device__ __forceinline__ void mma16(float c[4], const unsigned a[4], unsigned b0, unsigned b1) {
    asm volatile(
        "mma.sync.aligned.m16n8k16.row.col.f32.bf16.bf16.f32 "
        "{%0,%1,%2,%3}, {%4,%5,%6,%7}, {%8,%9}, {%0,%1,%2,%3};"
        : "+f"(c[0]), "+f"(c[1]), "+f"(c[2]), "+f"(c[3])
        : "r"(a[0]), "r"(a[1]), "r"(a[2]), "r"(a[3]), "r"(b0), "r"(b1));
}

__device__ __forceinline__ void split4(float4 v, uint2& hi, uint2& lo) {
    float f[4] = {v.x, v.y, v.z, v.w};
    unsigned short hs[4], ls[4];
#pragma unroll
    for (int i = 0; i < 4; i++) {
        __nv_bfloat16 h = __float2bfloat16_rn(f[i]);
        float r = f[i] - __bfloat162float(h);
        __nv_bfloat16 l = __float2bfloat16_rn(r);
        hs[i] = __bfloat16_as_ushort(h);
        ls[i] = __bfloat16_as_ushort(l);
    }
    hi.x = (unsigned)hs[0] | ((unsigned)hs[1] << 16);
    hi.y = (unsigned)hs[2] | ((unsigned)hs[3] << 16);
    lo.x = (unsigned)ls[0] | ((unsigned)ls[1] << 16);
    lo.y = (unsigned)ls[2] | ((unsigned)ls[3] << 16);
}

__global__ __launch_bounds__(256) void mma_gemm(const float* __restrict__ A,
                                                const float* __restrict__ B,
                                                const float* __restrict__ bias,
                                                float* __restrict__ C,
                                                int n, int K, int N, int act) {
    __shared__ __nv_bfloat16 As[2][2][BM * SAH];   // [buf][hi/lo]
    __shared__ __nv_bfloat16 Bs[2][2][BK * SBH];   // [buf][hi/lo], layout [k][n]

    int tid = threadIdx.x;
    int warp = tid >> 5, lane = tid & 31;
    int g = lane >> 2, tg = lane & 3;
    int wm = warp >> 1, wn = warp & 1;
    int row0 = blockIdx.x * BM, col0 = blockIdx.y * BN;

    // loader indices
    int la_r = tid >> 2, la_q = tid & 3;              // A: two rows (tid, tid+256)
    int lb_r = tid >> 4, lb_q = tid & 15;             // B

    float c[2][4][4];
#pragma unroll
    for (int mi = 0; mi < 2; mi++)
#pragma unroll
        for (int ni = 0; ni < 4; ni++)
#pragma unroll
            for (int q = 0; q < 4; q++) c[mi][ni][q] = 0.f;

    int nk = K / BK;
    float4 ra0, ra1, rb;

    // prologue: load tile 0
    {
        int gr0 = row0 + la_r;
        int gr1 = row0 + la_r + 64;
        ra0 = (gr0 < n) ? *(const float4*)&A[(size_t)gr0 * K + la_q * 4]
                        : make_float4(0.f, 0.f, 0.f, 0.f);
        ra1 = (gr1 < n) ? *(const float4*)&A[(size_t)gr1 * K + la_q * 4]
                        : make_float4(0.f, 0.f, 0.f, 0.f);
        rb = *(const float4*)&B[(size_t)lb_r * N + col0 + lb_q * 4];
    }
    {
        uint2 h, l;
        split4(ra0, h, l);
        *(uint2*)&As[0][0][la_r * SAH + la_q * 4] = h;
        *(uint2*)&As[0][1][la_r * SAH + la_q * 4] = l;
        split4(ra1, h, l);
        *(uint2*)&As[0][0][(la_r + 64) * SAH + la_q * 4] = h;
        *(uint2*)&As[0][1][(la_r + 64) * SAH + la_q * 4] = l;
        split4(rb, h, l);
        *(uint2*)&Bs[0][0][lb_r * SBH + lb_q * 4] = h;
        *(uint2*)&Bs[0][1][lb_r * SBH + lb_q * 4] = l;
    }
    __syncthreads();

    // ldmatrix lane addressing
    int a_row = wm * 32 + (lane & 15);
    int a_koff = (lane >> 4) * 8;
    int b_krow = lane & 15;
    int b_n0 = wn * 32 + (lane >> 4) * 8;

    for (int kb = 0; kb < nk; kb++) {
        int buf = kb & 1;
        bool more = (kb + 1 < nk);
        if (more) {
            int kk = (kb + 1) * BK;
            int gr0 = row0 + la_r;
            int gr1 = row0 + la_r + 64;
            ra0 = (gr0 < n) ? *(const float4*)&A[(size_t)gr0 * K + kk + la_q * 4]
                            : make_float4(0.f, 0.f, 0.f, 0.f);
            ra1 = (gr1 < n) ? *(const float4*)&A[(size_t)gr1 * K + kk + la_q * 4]
                            : make_float4(0.f, 0.f, 0.f, 0.f);
            rb = *(const float4*)&B[(size_t)(kk + lb_r) * N + col0 + lb_q * 4];
        }

        unsigned ah[2][4], al[2][4], bh[2][4], bl[2][4];
        ldsm_x4(ah[0], &As[buf][0][a_row * SAH + a_koff]);
        ldsm_x4(ah[1], &As[buf][0][(a_row + 16) * SAH + a_koff]);
        ldsm_x4(al[0], &As[buf][1][a_row * SAH + a_koff]);
        ldsm_x4(al[1], &As[buf][1][(a_row + 16) * SAH + a_koff]);
        ldsm_x4_t(bh[0], &Bs[buf][0][b_krow * SBH + b_n0]);
        ldsm_x4_t(bh[1], &Bs[buf][0][b_krow * SBH + b_n0 + 16]);
        ldsm_x4_t(bl[0], &Bs[buf][1][b_krow * SBH + b_n0]);
        ldsm_x4_t(bl[1], &Bs[buf][1][b_krow * SBH + b_n0 + 16]);

#pragma unroll
        for (int ni = 0; ni < 4; ni++) {
            int p = ni >> 1, w = ni & 1;
            unsigned bh0 = bh[p][w * 2], bh1 = bh[p][w * 2 + 1];
            unsigned bl0 = bl[p][w * 2], bl1 = bl[p][w * 2 + 1];
#pragma unroll
            for (int mi = 0; mi < 2; mi++) {
                mma16(c[mi][ni], ah[mi], bh0, bh1);   // hi*hi
                mma16(c[mi][ni], al[mi], bh0, bh1);   // lo*hi
                mma16(c[mi][ni], ah[mi], bl0, bl1);   // hi*lo
            }
        }

        if (more) {
            int nb = buf ^ 1;
            uint2 h, l;
            split4(ra0, h, l);
            *(uint2*)&As[nb][0][la_r * SAH + la_q * 4] = h;
            *(uint2*)&As[nb][1][la_r * SAH + la_q * 4] = l;
            split4(ra1, h, l);
            *(uint2*)&As[nb][0][(la_r + 64) * SAH + la_q * 4] = h;
            *(uint2*)&As[nb][1][(la_r + 64) * SAH + la_q * 4] = l;
            split4(rb, h, l);
            *(uint2*)&Bs[nb][0][lb_r * SBH + lb_q * 4] = h;
            *(uint2*)&Bs[nb][1][lb_r * SBH + lb_q * 4] = l;
            __syncthreads();
        }
    }

    // epilogue
#pragma unroll
    for (int mi = 0; mi < 2; mi++) {
#pragma unroll
        for (int ni = 0; ni < 4; ni++) {
            int r = row0 + wm * 32 + mi * 16 + g;
            int col = col0 + wn * 32 + ni * 8 + tg * 2;
            float b0v = bias ? __ldg(&bias[col]) : 0.f;
            float b1v = bias ? __ldg(&bias[col + 1]) : 0.f;
            if (r < n) {
                float v0 = c[mi][ni][0] + b0v;
                float v1 = c[mi][ni][1] + b1v;
                if (act) {
                    v0 = 0.5f * v0 * (1.0f + erff(v0 * 0.70710678118654752f));
                    v1 = 0.5f * v1 * (1.0f + erff(v1 * 0.70710678118654752f));
                }
                C[(size_t)r * N + col]     = v0;
                C[(size_t)r * N + col + 1] = v1;
            }
            if (r + 8 < n) {
                float v2 = c[mi][ni][2] + b0v;
                float v3 = c[mi][ni][3] + b1v;
                if (act) {
                    v2 = 0.5f * v2 * (1.0f + erff(v2 * 0.70710678118654752f));
                    v3 = 0.5f * v3 * (1.0f + erff(v3 * 0.70710678118654752f));
                }
                C[(size_t)(r + 8) * N + col]     = v2;
                C[(size_t)(r + 8) * N + col + 1] = v3;
            }
        }
    }
}

// ---------------- fused GATv2: single-pass online softmax + aggregation ----------------
// one warp per (node, head); xl values reused from score computation.
__global__ __launch_bounds__(256) void gat_fused_kernel(const int* __restrict__ ei,
                                                        const float* __restrict__ ea,
                                                        const float* __restrict__ We,
                                                        const float* __restrict__ att,
                                                        const float* __restrict__ bias) {
    int gw = (blockIdx.x * blockDim.x + threadIdx.x) >> 5;
    int lane = threadIdx.x & 31;
    if (gw >= NN * HEADS) return;
    int n = gw >> 2, h = gw & 3;
    int beg = g_rowptr[n], end = g_rowptr[n + 1];

    float xr[4], w0[4], w1[4], at[4];
#pragma unroll
    for (int k = 0; k < 4; k++) {
        int cc = h * H + lane + 32 * k;
        xr[k] = g_xr[(size_t)n * HH + cc];
        w0[k] = __ldg(&We[cc]);
        w1[k] = __ldg(&We[HH + cc]);
        at[k] = __ldg(&att[cc]);
    }
    float la0 = g_la[2 * n], la1 = g_la[2 * n + 1];

    float m = -1e30f, denom = 0.f;
    float acc[4] = {0.f, 0.f, 0.f, 0.f};

    for (int j = beg; j < end; j++) {
        int e = g_csr[j];
        int src; float a0, a1;
        if (e < NE) {
            src = __ldg(&ei[e]);
            a0 = __ldg(&ea[2 * e]);
            a1 = __ldg(&ea[2 * e + 1]);
        } else {
            src = n; a0 = la0; a1 = la1;
        }
        const float* xs = g_xl + (size_t)src * HH + h * H + lane;
        float xl[4];
        float p = 0.f;
#pragma unroll
        for (int k = 0; k < 4; k++) {
            xl[k] = __ldg(xs + 32 * k);
            float v = xl[k] + xr[k] + a0 * w0[k] + a1 * w1[k];
            v = v > 0.f ? v : 0.2f * v;
            p += v * at[k];
        }
#pragma unroll
        for (int o = 16; o; o >>= 1) p += __shfl_xor_sync(0xffffffffu, p, o);
        // online softmax (p is warp-uniform, no divergence)
        if (p > m) {
            float sc = __expf(m - p);
            denom *= sc;
#pragma unroll
            for (int k = 0; k < 4; k++) acc[k] *= sc;
            m = p;
        }
        float w = __expf(p - m);
        denom += w;
#pragma unroll
        for (int k = 0; k < 4; k++) acc[k] += w * xl[k];
    }

    float inv = 1.0f / (denom + 1e-16f);
    float* o = g_agg + (size_t)n * HH + h * H + lane;
#pragma unroll
    for (int k = 0; k < 4; k++) {
        float bv = bias ? __ldg(&bias[h * H + lane + 32 * k]) : 0.f;
        o[32 * k] = acc[k] * inv + bv;
    }
}

// layer-2: mean over heads + bias
__global__ void headmean_kernel(const float* __restrict__ bias2) {
    int idx = blockIdx.x * blockDim.x + threadIdx.x;
    if (idx >= NN * H) return;
    int n = idx >> 7, c = idx & 127;
    const float* a = g_agg + (size_t)n * HH;
    g_t[idx] = 0.25f * (a[c] + a[H + c] + a[2 * H + c] + a[3 * H + c]) + __ldg(&bias2[c]);
}

// warp-per-node LayerNorm: out = LN(a + res) * g + b
__global__ void ln_kernel(const float* __restrict__ a, const float* __restrict__ res,
                          const float* __restrict__ g, const float* __restrict__ b,
                          float* __restrict__ out) {
    int gw = (blockIdx.x * blockDim.x + threadIdx.x) >> 5;
    int lane = threadIdx.x & 31;
    if (gw >= NN) return;
    const float* pa = a + (size_t)gw * H;
    const float* pr = res + (size_t)gw * H;
    float v[4];
    float s = 0.f;
#pragma unroll
    for (int k = 0; k < 4; k++) {
        v[k] = pa[lane + 32 * k] + pr[lane + 32 * k];
        s += v[k];
    }
#pragma unroll
    for (int o = 16; o; o >>= 1) s += __shfl_xor_sync(0xffffffffu, s, o);
    float mu = s * (1.0f / 128.0f);
    float q = 0.f;
#pragma unroll
    for (int k = 0; k < 4; k++) {
        float d = v[k] - mu;
        q += d * d;
    }
#pragma unroll
    for (int o = 16; o; o >>= 1) q += __shfl_xor_sync(0xffffffffu, q, o);
    float r = rsqrtf(q * (1.0f / 128.0f) + 1e-5f);
    float* po = out + (size_t)gw * H;
#pragma unroll
    for (int k = 0; k < 4; k++) {
        int cc = lane + 32 * k;
        po[cc] = (v[k] - mu) * r * __ldg(&g[cc]) + __ldg(&b[cc]);
    }
}

// ---------------- host ----------------
static void* sym(const void* s) {
    void* p = 0;
    cudaGetSymbolAddress(&p, s);
    return p;
}

extern "C" void kernel_launch(void* const* d_in, const int* in_sizes, int n_in,
                              void* d_out, int out_size) {
    const float* x        = (const float*)d_in[0];
    const int*   ei       = (const int*)d_in[1];
    const float* ea       = (const float*)d_in[2];
    const float* emb_w    = (const float*)d_in[3];
    const float* emb_b    = (const float*)d_in[4];
    const float* lin_l    = (const float*)d_in[5];
    const float* lin_r    = (const float*)d_in[6];
    const float* lin_edge = (const float*)d_in[7];
    const float* att      = (const float*)d_in[8];
    const float* cbias01  = (const float*)d_in[9];
    const float* cbias2   = (const float*)d_in[10];
    const float* proj_w   = (const float*)d_in[11];
    const float* proj_b   = (const float*)d_in[12];
    const float* n1_g     = (const float*)d_in[13];
    const float* n1_b     = (const float*)d_in[14];
    const float* n2_g     = (const float*)d_in[15];
    const float* n2_b     = (const float*)d_in[16];
    const float* ffn_w1   = (const float*)d_in[17];
    const float* ffn_b1   = (const float*)d_in[18];
    const float* ffn_w2   = (const float*)d_in[19];
    const float* ffn_b2   = (const float*)d_in[20];

    float* p_h   = (float*)sym(g_h);
    float* p_t   = (float*)sym(g_t);
    float* p_xl  = (float*)sym(g_xl);
    float* p_xr  = (float*)sym(g_xr);
    float* p_agg = (float*)sym(g_agg);
    float* p_ffn = (float*)sym(g_ffn);

    // graph setup
    int nblk = (NN + 1023) / 1024;
    zero_kernel<<<(NN + 255) / 256, 256>>>();
    deg_kernel<<<(NE + 255) / 256, 256>>>(ei, ea);
    loopattr_kernel<<<(NN + 255) / 256, 256>>>();
    scan1_kernel<<<nblk, 1024>>>();
    scan2_kernel<<<1, 32>>>(nblk);
    scan3_kernel<<<(NN + 255) / 256, 256>>>();
    scatter_kernel<<<(NE2 + 255) / 256, 256>>>(ei);

    // embedding: h = x @ emb_w + emb_b
    {
        dim3 grid((NN + BM - 1) / BM, H / BN);
        mma_gemm<<<grid, 256>>>(x, emb_w, emb_b, p_h, NN, 16, H, 0);
    }

    for (int i = 0; i < 3; i++) {
        const float* Wl = lin_l + (size_t)i * H * HH;
        const float* Wr = lin_r + (size_t)i * H * HH;
        const float* We = lin_edge + (size_t)i * 2 * HH;
        const float* At = att + (size_t)i * HEADS * H;

        dim3 g512((NN + BM - 1) / BM, HH / BN);
        mma_gemm<<<g512, 256>>>(p_h, Wl, 0, p_xl, NN, H, HH, 0);
        mma_gemm<<<g512, 256>>>(p_h, Wr, 0, p_xr, NN, H, HH, 0);

        {
            long warps = (long)NN * HEADS;
            long thr = warps * 32;
            const float* bias = (i < 2) ? (cbias01 + (size_t)i * HH) : 0;
            gat_fused_kernel<<<(int)((thr + 255) / 256), 256>>>(ei, ea, We, At, bias);
        }

        if (i < 2) {
            dim3 gp((NN + BM - 1) / BM, H / BN);
            mma_gemm<<<gp, 256>>>(p_agg, proj_w + (size_t)i * HH * H,
                                  proj_b + (size_t)i * H, p_t, NN, HH, H, 0);
        } else {
            headmean_kernel<<<(NN * H + 255) / 256, 256>>>(cbias2);
        }

        ln_kernel<<<(NN * 32 + 255) / 256, 256>>>(p_t, p_h, n1_g + (size_t)i * H,
                                                  n1_b + (size_t)i * H, p_h);

        dim3 gf1((NN + BM - 1) / BM, 256 / BN);
        mma_gemm<<<gf1, 256>>>(p_h, ffn_w1 + (size_t)i * H * 256,
                               ffn_b1 + (size_t)i * 256, p_ffn, NN, H, 256, 1);
        dim3 gf2((NN + BM - 1) / BM, H / BN);
        mma_gemm<<<gf2, 256>>>(p_ffn, ffn_w2 + (size_t)i * 256 * H,
                               ffn_b2 + (size_t)i * H, p_t, NN, 256, H, 0);

        float* out_ptr = (i == 2) ? (float*)d_out : p_h;
        ln_kernel<<<(NN * 32 + 255) / 256, 256>>>(p_t, p_h, n2_g + (size_t)i * H,
                                                  n2_b + (size_t)i * H, out_ptr);
    }
}